// round 10
// baseline (speedup 1.0000x reference)
#include <cuda_runtime.h>
#include <cuda_fp16.h>
#include <math_constants.h>

// Fused GAT forward. N=50000, deg=16 (CSR), H=4, D=32.
//
// K1 (convert): in_feat fp32 [N,128] -> g_feat16 fp16 words, uint4 stores.
// K2 (gat), one warp per node, reg-capped for occupancy:
//   phase 1 (lanes 0..15): one edge each, all-4-head scores via float4
//     attn loads, xor-shuffle softmax over the 16-edge group.
//     Park cols s_col[16] and alpha pairs s_ap[p][edge]={a_p, a_{p+2}}.
//   phase 2 (all 32 lanes): lane owns fp16 words {col*64+l} (dims 2l,2l+1,
//     head l>>4) and {col*64+32+l} (dims 64+2l, head 2+(l>>4)).
//     Each gather LDG.32 spans exactly ONE 128B line (cross-LDG 1.0 cyc/line
//     instead of 2.07 within-LDG replay). Per 4-edge group: 1 broadcast
//     LDS.128 (cols) + 1 LDS.128 (alpha pairs); per edge 2 LDG.32 + 2 cvt +
//     4 FFMA. fp32 accumulate, two coalesced STG.64 per lane.
//   __launch_bounds__(256, 6) caps regs ~42 -> ~75% occupancy (R8's 62-reg
//   pair kernel collapsed occ to 44% and went latency-bound).

#define NEG_SLOPE 0.2f
#define WPB 8
#define MAX_N 50000

__device__ __align__(16) unsigned int g_feat16[(size_t)MAX_N * 64];

// ---------------- fp32 -> fp16 conversion pre-pass ----------------
__global__ void __launch_bounds__(256)
gat_convert_kernel(const float4* __restrict__ src, int n8)
{
    int i = blockIdx.x * blockDim.x + threadIdx.x;
    if (i >= n8) return;
    const float4 a = src[2 * i];
    const float4 b = src[2 * i + 1];
    const __half2 h0 = __floats2half2_rn(a.x, a.y);
    const __half2 h1 = __floats2half2_rn(a.z, a.w);
    const __half2 h2 = __floats2half2_rn(b.x, b.y);
    const __half2 h3 = __floats2half2_rn(b.z, b.w);
    uint4 u;
    u.x = *reinterpret_cast<const unsigned int*>(&h0);
    u.y = *reinterpret_cast<const unsigned int*>(&h1);
    u.z = *reinterpret_cast<const unsigned int*>(&h2);
    u.w = *reinterpret_cast<const unsigned int*>(&h3);
    ((uint4*)g_feat16)[i] = u;
}

// ---------------- main fused GAT kernel ----------------
__global__ void __launch_bounds__(WPB * 32, 6)
fused_gat_node_kernel(const float* __restrict__ attn_row,   // [N,4]
                      const float* __restrict__ attn_col,   // [N,4]
                      const int*   __restrict__ row_indptr, // [N+1]
                      const int*   __restrict__ col_idx,    // [E]
                      float*       __restrict__ out,        // [N,4,32]
                      int n)
{
    __shared__ __align__(16) int    s_col[WPB][16];
    // [warp][p][edge(16 padded to 18)] : {alpha_p, alpha_{p+2}}
    __shared__ __align__(16) float2 s_ap[WPB][2][18];

    const int lane = threadIdx.x & 31;
    const int w    = threadIdx.x >> 5;
    const int node = blockIdx.x * WPB + w;
    if (node >= n) return;

    const int start = __ldg(&row_indptr[node]);
    const int deg   = __ldg(&row_indptr[node + 1]) - start;   // == 16 here

    // ---- per-edge scores, all 4 heads (lanes 0..15) ----
    const float4 ar = __ldg((const float4*)attn_row + node);

    int col = 0;
    float s0 = -CUDART_INF_F, s1 = -CUDART_INF_F,
          s2 = -CUDART_INF_F, s3 = -CUDART_INF_F;

    const bool edge_lane = (lane < 16) && (lane < deg);
    if (edge_lane) {
        col = __ldg(&col_idx[start + lane]);
        const float4 ac = __ldg((const float4*)attn_col + col);
        float t0 = ar.x + ac.x, t1 = ar.y + ac.y;
        float t2 = ar.z + ac.z, t3 = ar.w + ac.w;
        s0 = (t0 > 0.0f) ? t0 : NEG_SLOPE * t0;
        s1 = (t1 > 0.0f) ? t1 : NEG_SLOPE * t1;
        s2 = (t2 > 0.0f) ? t2 : NEG_SLOPE * t2;
        s3 = (t3 > 0.0f) ? t3 : NEG_SLOPE * t3;
    }

    // ---- shuffle softmax over the 16-edge group (xor 8,4,2,1) ----
    float m0 = s0, m1 = s1, m2 = s2, m3 = s3;
    #pragma unroll
    for (int k = 8; k > 0; k >>= 1) {
        m0 = fmaxf(m0, __shfl_xor_sync(0xffffffffu, m0, k));
        m1 = fmaxf(m1, __shfl_xor_sync(0xffffffffu, m1, k));
        m2 = fmaxf(m2, __shfl_xor_sync(0xffffffffu, m2, k));
        m3 = fmaxf(m3, __shfl_xor_sync(0xffffffffu, m3, k));
    }

    float e0 = 0.f, e1 = 0.f, e2 = 0.f, e3 = 0.f;
    if (edge_lane) {
        e0 = __expf(s0 - m0);
        e1 = __expf(s1 - m1);
        e2 = __expf(s2 - m2);
        e3 = __expf(s3 - m3);
    }

    float d0 = e0, d1 = e1, d2 = e2, d3 = e3;
    #pragma unroll
    for (int k = 8; k > 0; k >>= 1) {
        d0 += __shfl_xor_sync(0xffffffffu, d0, k);
        d1 += __shfl_xor_sync(0xffffffffu, d1, k);
        d2 += __shfl_xor_sync(0xffffffffu, d2, k);
        d3 += __shfl_xor_sync(0xffffffffu, d3, k);
    }

    if (lane < 16) {
        const float a0 = edge_lane ? __fdividef(e0, d0) : 0.f;
        const float a1 = edge_lane ? __fdividef(e1, d1) : 0.f;
        const float a2 = edge_lane ? __fdividef(e2, d2) : 0.f;
        const float a3 = edge_lane ? __fdividef(e3, d3) : 0.f;
        s_col[w][lane]   = col;
        s_ap[w][0][lane] = make_float2(a0, a2);   // heads (0,2)
        s_ap[w][1][lane] = make_float2(a1, a3);   // heads (1,3)
    }
    __syncwarp(0xffffffffu);

    // ---- aggregation: lane owns words {l} and {32+l} of each 64-word row ----
    const int p = lane >> 4;    // low-word head p, high-word head p+2
    const int4*   __restrict__ cp = (const int4*)s_col[w];
    const float4* __restrict__ ap = (const float4*)&s_ap[w][p][0];
    const unsigned int* __restrict__ fb = g_feat16;

    float2 accL = make_float2(0.f, 0.f);
    float2 accH = make_float2(0.f, 0.f);

    #pragma unroll
    for (int j4 = 0; j4 < 4; ++j4) {
        const int4   c  = cp[j4];          // 4 neighbor ids (broadcast)
        const float4 A0 = ap[j4 * 2];      // edges 0,1: {aL,aH,aL,aH}
        const float4 A1 = ap[j4 * 2 + 1];  // edges 2,3

        unsigned b, u0, u1;
        float2 f0, f1;

        b  = (unsigned)c.x * 64u;
        u0 = __ldg(fb + b + lane);
        u1 = __ldg(fb + b + 32 + lane);
        f0 = __half22float2(*reinterpret_cast<const __half2*>(&u0));
        f1 = __half22float2(*reinterpret_cast<const __half2*>(&u1));
        accL.x = fmaf(A0.x, f0.x, accL.x); accL.y = fmaf(A0.x, f0.y, accL.y);
        accH.x = fmaf(A0.y, f1.x, accH.x); accH.y = fmaf(A0.y, f1.y, accH.y);

        b  = (unsigned)c.y * 64u;
        u0 = __ldg(fb + b + lane);
        u1 = __ldg(fb + b + 32 + lane);
        f0 = __half22float2(*reinterpret_cast<const __half2*>(&u0));
        f1 = __half22float2(*reinterpret_cast<const __half2*>(&u1));
        accL.x = fmaf(A0.z, f0.x, accL.x); accL.y = fmaf(A0.z, f0.y, accL.y);
        accH.x = fmaf(A0.w, f1.x, accH.x); accH.y = fmaf(A0.w, f1.y, accH.y);

        b  = (unsigned)c.z * 64u;
        u0 = __ldg(fb + b + lane);
        u1 = __ldg(fb + b + 32 + lane);
        f0 = __half22float2(*reinterpret_cast<const __half2*>(&u0));
        f1 = __half22float2(*reinterpret_cast<const __half2*>(&u1));
        accL.x = fmaf(A1.x, f0.x, accL.x); accL.y = fmaf(A1.x, f0.y, accL.y);
        accH.x = fmaf(A1.y, f1.x, accH.x); accH.y = fmaf(A1.y, f1.y, accH.y);

        b  = (unsigned)c.w * 64u;
        u0 = __ldg(fb + b + lane);
        u1 = __ldg(fb + b + 32 + lane);
        f0 = __half22float2(*reinterpret_cast<const __half2*>(&u0));
        f1 = __half22float2(*reinterpret_cast<const __half2*>(&u1));
        accL.x = fmaf(A1.z, f0.x, accL.x); accL.y = fmaf(A1.z, f0.y, accL.y);
        accH.x = fmaf(A1.w, f1.x, accH.x); accH.y = fmaf(A1.w, f1.y, accH.y);
    }

    // out[node]: float2 at dims {2l,2l+1} and {64+2l,65+2l} (coalesced)
    float2* op = (float2*)out + (size_t)node * 64;
    op[lane]      = accL;
    op[32 + lane] = accH;
}

extern "C" void kernel_launch(void* const* d_in, const int* in_sizes, int n_in,
                              void* d_out, int out_size)
{
    const float* attn_row   = (const float*)d_in[0];
    const float* attn_col   = (const float*)d_in[1];
    const float* in_feat    = (const float*)d_in[2];
    const int*   row_indptr = (const int*)  d_in[3];
    const int*   col_idx    = (const int*)  d_in[4];
    float*       out        = (float*)      d_out;

    const int n  = in_sizes[3] - 1;   // N from indptr length
    const int n8 = in_sizes[2] / 8;   // uint4 count of fp16 copy

    gat_convert_kernel<<<(n8 + 255) / 256, 256>>>((const float4*)in_feat, n8);

    const int blocks = (n + WPB - 1) / WPB;
    fused_gat_node_kernel<<<blocks, WPB * 32>>>(attn_row, attn_col,
                                                row_indptr, col_idx, out, n);
}

// round 11
// speedup vs baseline: 1.1240x; 1.1240x over previous
#include <cuda_runtime.h>
#include <cuda_fp16.h>
#include <math_constants.h>

// Fused GAT forward. N=50000, deg=16 (CSR), H=4, D=32.
//
// K1 (convert): in_feat fp32 [N,128] -> g_feat16 fp16 words, uint4 stores.
// K2 (gat), one warp per NODE PAIR (R8 structure, reg-capped):
//   phase 1: lanes 0..15 = edges of node A, 16..31 = node B. float4 attn
//     loads, xor-shuffle softmax per 16-lane half (softmax cost amortized
//     over 2 nodes). Park cols + alpha pairs {a_p, a_{p+2}} in smem.
//   phase 2: loop over the 2 nodes; lane owns fp16 words {col*64+l} and
//     {col*64+32+l} -> every gather LDG.32 is fully coalesced into exactly
//     ONE 128B line (1.0 cyc/line). Per 4-edge group: 1 broadcast LDS.128
//     (cols) + 2 LDS.128 (alphas); per edge 2 LDG.32 + 2 cvt + 4 FFMA.
//   __launch_bounds__(256, 5) caps regs ~48: R8 at 62 regs ran 44% occ and
//   left its 16.4us L1-busy floor exposed at 62% utilization.

#define NEG_SLOPE 0.2f
#define WPB 8
#define MAX_N 50000

__device__ __align__(16) unsigned int g_feat16[(size_t)MAX_N * 64];

// ---------------- fp32 -> fp16 conversion pre-pass ----------------
__global__ void __launch_bounds__(256)
gat_convert_kernel(const float4* __restrict__ src, int n8)
{
    int i = blockIdx.x * blockDim.x + threadIdx.x;
    if (i >= n8) return;
    const float4 a = src[2 * i];
    const float4 b = src[2 * i + 1];
    const __half2 h0 = __floats2half2_rn(a.x, a.y);
    const __half2 h1 = __floats2half2_rn(a.z, a.w);
    const __half2 h2 = __floats2half2_rn(b.x, b.y);
    const __half2 h3 = __floats2half2_rn(b.z, b.w);
    uint4 u;
    u.x = *reinterpret_cast<const unsigned int*>(&h0);
    u.y = *reinterpret_cast<const unsigned int*>(&h1);
    u.z = *reinterpret_cast<const unsigned int*>(&h2);
    u.w = *reinterpret_cast<const unsigned int*>(&h3);
    ((uint4*)g_feat16)[i] = u;
}

// ---------------- main fused GAT kernel ----------------
__global__ void __launch_bounds__(WPB * 32, 5)
fused_gat_pair_kernel(const float* __restrict__ attn_row,   // [N,4]
                      const float* __restrict__ attn_col,   // [N,4]
                      const int*   __restrict__ row_indptr, // [N+1]
                      const int*   __restrict__ col_idx,    // [E]
                      float*       __restrict__ out,        // [N,4,32]
                      int n)
{
    __shared__ __align__(16) int    s_col[WPB][32];
    // [warp][p][node-half][edge(16 padded to 18)] : {alpha_p, alpha_{p+2}}
    __shared__ __align__(16) float2 s_ap[WPB][2][2][18];

    const int lane  = threadIdx.x & 31;
    const int w     = threadIdx.x >> 5;
    const int pair  = blockIdx.x * WPB + w;
    const int node0 = pair * 2;
    if (node0 >= n) return;

    const int  half = lane >> 4;        // which node of the pair my lane scores
    const int  el   = lane & 15;        // edge slot within that node
    const int  nodeu = node0 + half;
    const bool nvalid = (nodeu < n);
    const int  node  = nvalid ? nodeu : (n - 1);   // clamp for safe loads

    const int start = __ldg(&row_indptr[node]);
    const int deg   = __ldg(&row_indptr[node + 1]) - start;

    // ---- per-edge scores, all 4 heads ----
    const float4 ar = __ldg((const float4*)attn_row + node);

    int col = 0;
    float s0 = -CUDART_INF_F, s1 = -CUDART_INF_F,
          s2 = -CUDART_INF_F, s3 = -CUDART_INF_F;

    const bool edge_lane = nvalid && (el < deg);
    if (edge_lane) {
        col = __ldg(&col_idx[start + el]);
        const float4 ac = __ldg((const float4*)attn_col + col);
        float t0 = ar.x + ac.x, t1 = ar.y + ac.y;
        float t2 = ar.z + ac.z, t3 = ar.w + ac.w;
        s0 = (t0 > 0.0f) ? t0 : NEG_SLOPE * t0;
        s1 = (t1 > 0.0f) ? t1 : NEG_SLOPE * t1;
        s2 = (t2 > 0.0f) ? t2 : NEG_SLOPE * t2;
        s3 = (t3 > 0.0f) ? t3 : NEG_SLOPE * t3;
    }

    // ---- shuffle softmax per 16-lane half (xor 8,4,2,1 stays in half) ----
    float m0 = s0, m1 = s1, m2 = s2, m3 = s3;
    #pragma unroll
    for (int k = 8; k > 0; k >>= 1) {
        m0 = fmaxf(m0, __shfl_xor_sync(0xffffffffu, m0, k));
        m1 = fmaxf(m1, __shfl_xor_sync(0xffffffffu, m1, k));
        m2 = fmaxf(m2, __shfl_xor_sync(0xffffffffu, m2, k));
        m3 = fmaxf(m3, __shfl_xor_sync(0xffffffffu, m3, k));
    }

    float e0 = 0.f, e1 = 0.f, e2 = 0.f, e3 = 0.f;
    if (edge_lane) {
        e0 = __expf(s0 - m0);
        e1 = __expf(s1 - m1);
        e2 = __expf(s2 - m2);
        e3 = __expf(s3 - m3);
    }

    float d0 = e0, d1 = e1, d2 = e2, d3 = e3;
    #pragma unroll
    for (int k = 8; k > 0; k >>= 1) {
        d0 += __shfl_xor_sync(0xffffffffu, d0, k);
        d1 += __shfl_xor_sync(0xffffffffu, d1, k);
        d2 += __shfl_xor_sync(0xffffffffu, d2, k);
        d3 += __shfl_xor_sync(0xffffffffu, d3, k);
    }

    s_col[w][lane]       = col;
    s_ap[w][0][half][el] = make_float2(__fdividef(e0, d0), __fdividef(e2, d2));
    s_ap[w][1][half][el] = make_float2(__fdividef(e1, d1), __fdividef(e3, d3));
    __syncwarp(0xffffffffu);

    // ---- aggregation: lane owns fp16 words {l} and {32+l} of each row ----
    const int p = half;   // low-word head p, high-word head p+2
    const unsigned int* __restrict__ fb = g_feat16;

    #pragma unroll
    for (int n2 = 0; n2 < 2; ++n2) {
        const int nodeX = node0 + n2;
        if (nodeX >= n) break;

        const int4*   __restrict__ cp = (const int4*)&s_col[w][n2 * 16];
        const float4* __restrict__ ap = (const float4*)&s_ap[w][p][n2][0];

        float2 accL = make_float2(0.f, 0.f);
        float2 accH = make_float2(0.f, 0.f);

        #pragma unroll
        for (int j4 = 0; j4 < 4; ++j4) {
            const int4   c  = cp[j4];          // 4 neighbor ids (broadcast)
            const float4 A0 = ap[j4 * 2];      // edges 0,1: {aL,aH,aL,aH}
            const float4 A1 = ap[j4 * 2 + 1];  // edges 2,3

            unsigned b, u0, u1;
            float2 f0, f1;

            b  = (unsigned)c.x * 64u;
            u0 = __ldg(fb + b + lane);
            u1 = __ldg(fb + b + 32 + lane);
            f0 = __half22float2(*reinterpret_cast<const __half2*>(&u0));
            f1 = __half22float2(*reinterpret_cast<const __half2*>(&u1));
            accL.x = fmaf(A0.x, f0.x, accL.x); accL.y = fmaf(A0.x, f0.y, accL.y);
            accH.x = fmaf(A0.y, f1.x, accH.x); accH.y = fmaf(A0.y, f1.y, accH.y);

            b  = (unsigned)c.y * 64u;
            u0 = __ldg(fb + b + lane);
            u1 = __ldg(fb + b + 32 + lane);
            f0 = __half22float2(*reinterpret_cast<const __half2*>(&u0));
            f1 = __half22float2(*reinterpret_cast<const __half2*>(&u1));
            accL.x = fmaf(A0.z, f0.x, accL.x); accL.y = fmaf(A0.z, f0.y, accL.y);
            accH.x = fmaf(A0.w, f1.x, accH.x); accH.y = fmaf(A0.w, f1.y, accH.y);

            b  = (unsigned)c.z * 64u;
            u0 = __ldg(fb + b + lane);
            u1 = __ldg(fb + b + 32 + lane);
            f0 = __half22float2(*reinterpret_cast<const __half2*>(&u0));
            f1 = __half22float2(*reinterpret_cast<const __half2*>(&u1));
            accL.x = fmaf(A1.x, f0.x, accL.x); accL.y = fmaf(A1.x, f0.y, accL.y);
            accH.x = fmaf(A1.y, f1.x, accH.x); accH.y = fmaf(A1.y, f1.y, accH.y);

            b  = (unsigned)c.w * 64u;
            u0 = __ldg(fb + b + lane);
            u1 = __ldg(fb + b + 32 + lane);
            f0 = __half22float2(*reinterpret_cast<const __half2*>(&u0));
            f1 = __half22float2(*reinterpret_cast<const __half2*>(&u1));
            accL.x = fmaf(A1.z, f0.x, accL.x); accL.y = fmaf(A1.z, f0.y, accL.y);
            accH.x = fmaf(A1.w, f1.x, accH.x); accH.y = fmaf(A1.w, f1.y, accH.y);
        }

        // out[nodeX]: float2 at dims {2l,2l+1} and {64+2l,65+2l} (coalesced)
        float2* op = (float2*)out + (size_t)nodeX * 64;
        op[lane]      = accL;
        op[32 + lane] = accH;
    }
}

extern "C" void kernel_launch(void* const* d_in, const int* in_sizes, int n_in,
                              void* d_out, int out_size)
{
    const float* attn_row   = (const float*)d_in[0];
    const float* attn_col   = (const float*)d_in[1];
    const float* in_feat    = (const float*)d_in[2];
    const int*   row_indptr = (const int*)  d_in[3];
    const int*   col_idx    = (const int*)  d_in[4];
    float*       out        = (float*)      d_out;

    const int n  = in_sizes[3] - 1;   // N from indptr length
    const int n8 = in_sizes[2] / 8;   // uint4 count of fp16 copy

    gat_convert_kernel<<<(n8 + 255) / 256, 256>>>((const float4*)in_feat, n8);

    const int pairs  = (n + 1) / 2;
    const int blocks = (pairs + WPB - 1) / WPB;
    fused_gat_pair_kernel<<<blocks, WPB * 32>>>(attn_row, attn_col,
                                                row_indptr, col_idx, out, n);
}